// round 12
// baseline (speedup 1.0000x reference)
#include <cuda_runtime.h>
#include <cuda_bf16.h>

#define N_NODES 1024
#define ROWPAD 36                      // 32 data + 4 pad floats per staged row
#define BUF_FLOATS (128 * ROWPAD)      // one 1-row buffer (128 j)
#define NBUF 4
#define EDGE_SMEM_BYTES ((NBUF * BUF_FLOATS + 128) * 4)

typedef unsigned long long u64;

// ---------------- packed f32x2 helpers (sm_103a) ----------------
__device__ __forceinline__ u64 pack2(float lo, float hi) {
    u64 r; asm("mov.b64 %0, {%1, %2};" : "=l"(r) : "f"(lo), "f"(hi)); return r;
}
__device__ __forceinline__ void unpack2(u64 v, float& lo, float& hi) {
    asm("mov.b64 {%0, %1}, %2;" : "=f"(lo), "=f"(hi) : "l"(v));
}
__device__ __forceinline__ u64 ffma2(u64 a, u64 b, u64 c) {
    u64 d; asm("fma.rn.f32x2 %0, %1, %2, %3;" : "=l"(d) : "l"(a), "l"(b), "l"(c)); return d;
}
__device__ __forceinline__ unsigned smem_u32(const void* p) {
    unsigned a;
    asm("{ .reg .u64 t; cvta.to.shared.u64 t, %1; cvt.u32.u64 %0, t; }" : "=r"(a) : "l"(p));
    return a;
}

// ---------------- constant weights for edge kernel ----------------
__constant__ float cWe1[96 * 16];
__constant__ float cbe2[16];
__constant__ float cWe2[16 * 16];

// ---------------- device scratch ----------------
__device__ __align__(16) float g_pa[N_NODES * 16];
__device__ __align__(16) float g_pb[N_NODES * 16];
__device__ __align__(16) float g_msga[N_NODES * 16];
__device__ __align__(16) float g_msgb[N_NODES * 16];

// ============ Kernel A: zero accumulators + per-node precompute ============
__global__ __launch_bounds__(256) void prep_kernel(const float* __restrict__ na,
                                                   const float* __restrict__ nb,
                                                   const float* __restrict__ We1,
                                                   const float* __restrict__ be1) {
    __shared__ __align__(16) float sw[32 * 16];
    __shared__ __align__(16) float sb[16];

    const int b    = blockIdx.x;
    const bool isA = (b < 16);
    const int bb   = isA ? b : b - 16;
    const int tid  = threadIdx.x;

    reinterpret_cast<float2*>(sw)[tid] =
        reinterpret_cast<const float2*>(We1 + (isA ? 0 : 512))[tid];
    if (tid < 16) sb[tid] = isA ? be1[tid] : 0.0f;

    reinterpret_cast<float4*>((isA ? g_msga : g_msgb) + bb * 1024)[tid] =
        make_float4(0.f, 0.f, 0.f, 0.f);
    __syncthreads();

    const int node = bb * 64 + (tid >> 2);
    const int cg   = (tid & 3) * 4;

    const float* row = (isA ? na : nb) + node * 32;
    float x[32];
#pragma unroll
    for (int u = 0; u < 8; u++) {
        float4 v = reinterpret_cast<const float4*>(row)[u];
        x[u * 4 + 0] = v.x; x[u * 4 + 1] = v.y; x[u * 4 + 2] = v.z; x[u * 4 + 3] = v.w;
    }

    float4 acc = *reinterpret_cast<const float4*>(&sb[cg]);
#pragma unroll
    for (int k = 0; k < 32; k++) {
        const float xs = x[k];
        float4 w = *reinterpret_cast<const float4*>(&sw[k * 16 + cg]);
        acc.x = fmaf(xs, w.x, acc.x);
        acc.y = fmaf(xs, w.y, acc.y);
        acc.z = fmaf(xs, w.z, acc.z);
        acc.w = fmaf(xs, w.w, acc.w);
    }

    float* dst = (isA ? g_pa : g_pb) + node * 16 + cg;
    *reinterpret_cast<float4*>(dst) = acc;
}

// Butterfly channel-merging reduction.
__device__ __forceinline__ int chan16(int lane) {
    return ((lane & 1) ? 8 : 0) | ((lane & 2) ? 4 : 0) |
           ((lane & 4) ? 2 : 0) | ((lane & 8) ? 1 : 0);
}

__device__ __forceinline__ float warp_reduce16(float* v, int lane) {
    const unsigned FULL = 0xffffffffu;
    {
        bool hi = (lane & 1);
#pragma unroll
        for (int k = 0; k < 8; k++) {
            float send  = hi ? v[k] : v[k + 8];
            float other = __shfl_xor_sync(FULL, send, 1);
            v[k] = (hi ? v[k + 8] : v[k]) + other;
        }
    }
    {
        bool hi = (lane & 2);
#pragma unroll
        for (int k = 0; k < 4; k++) {
            float send  = hi ? v[k] : v[k + 4];
            float other = __shfl_xor_sync(FULL, send, 2);
            v[k] = (hi ? v[k + 4] : v[k]) + other;
        }
    }
    {
        bool hi = (lane & 4);
#pragma unroll
        for (int k = 0; k < 2; k++) {
            float send  = hi ? v[k] : v[k + 2];
            float other = __shfl_xor_sync(FULL, send, 4);
            v[k] = (hi ? v[k + 2] : v[k]) + other;
        }
    }
    {
        bool hi = (lane & 8);
        float send  = hi ? v[0] : v[1];
        float other = __shfl_xor_sync(FULL, send, 8);
        v[0] = (hi ? v[1] : v[0]) + other;
    }
    v[0] += __shfl_xor_sync(FULL, v[0], 16);
    return v[0];
}

// ============ Kernel B: edge MLP, 4-buffer single-sync cp.async pipeline ============
// Slot restaged at iter `it` (slot (it+3)%4) was last read at iter it-1; the
// top-of-loop __syncthreads separates them, so no trailing sync is needed.
__global__ __launch_bounds__(128) void edge_kernel(const float* __restrict__ edges,
                                                   float* __restrict__ out_e,
                                                   int y_off) {
    extern __shared__ __align__(16) float smem[];
    float* s_pa = smem + NBUF * BUF_FLOATS;

    const int tid  = threadIdx.x;
    const int lane = tid & 31;
    const int j0   = blockIdx.x * 128;
    const int j    = j0 + tid;
    const int i0   = (y_off + blockIdx.y) * 8;

    s_pa[tid] = g_pa[i0 * 16 + tid];

    const u64* cWe1p = reinterpret_cast<const u64*>(cWe1);
    const u64* cWe2p = reinterpret_cast<const u64*>(cWe2);

    u64 pb2[8];
    {
        const float4* p4 = reinterpret_cast<const float4*>(g_pb + j * 16);
#pragma unroll
        for (int u = 0; u < 4; u++) {
            float4 v = p4[u];
            pb2[2 * u]     = pack2(v.x, v.y);
            pb2[2 * u + 1] = pack2(v.z, v.w);
        }
    }
    u64 be2p[8];
#pragma unroll
    for (int p = 0; p < 8; p++) be2p[p] = pack2(cbe2[2 * p], cbe2[2 * p + 1]);

    float msgb[16];
#pragma unroll
    for (int c = 0; c < 16; c++) msgb[c] = 0.0f;

    auto stage = [&](int i_row, int slot) {
        const float* srcbase = edges + ((size_t)i_row * 1024 + j0) * 32;
        unsigned dstbase = smem_u32(smem + slot * BUF_FLOATS);
#pragma unroll
        for (int q = 0; q < 8; q++) {
            int g   = q * 128 + tid;
            int row = g >> 3;
            int kk  = g & 7;
            unsigned d = dstbase + (unsigned)(row * ROWPAD + kk * 4) * 4u;
            const float* s = srcbase + g * 4;
            asm volatile("cp.async.cg.shared.global [%0], [%1], 16;" :: "r"(d), "l"(s));
        }
        asm volatile("cp.async.commit_group;");
    };

    // prologue: fill prefetch distance 3
    stage(i0 + 0, 0);
    stage(i0 + 1, 1);
    stage(i0 + 2, 2);

#pragma unroll 1
    for (int it = 0; it < 8; it++) {
        const int i = i0 + it;
        const int slot = it & 3;

        // groups in flight after prologue/steady-state staging:
        if (it <= 4)      asm volatile("cp.async.wait_group 2;");
        else if (it == 5) asm volatile("cp.async.wait_group 2;");
        else if (it == 6) asm volatile("cp.async.wait_group 1;");
        else              asm volatile("cp.async.wait_group 0;");
        __syncthreads();   // single barrier: also orders prior-iter reads vs restage below

        if (it + 3 < 8) stage(i0 + it + 3, (it + 3) & 3);

        const float* myrow = smem + slot * BUF_FLOATS + tid * ROWPAD;

        // layer 1: h = pa[i] + pb[j] + edge @ We1[64:96]
        u64 h2[8];
#pragma unroll
        for (int p = 0; p < 8; p++) {
            float alo = s_pa[it * 16 + 2 * p];
            float ahi = s_pa[it * 16 + 2 * p + 1];
            float blo, bhi; unpack2(pb2[p], blo, bhi);
            h2[p] = pack2(alo + blo, ahi + bhi);
        }

#pragma unroll
        for (int u = 0; u < 8; u++) {
            float4 x = *reinterpret_cast<const float4*>(myrow + u * 4);
#pragma unroll
            for (int kk = 0; kk < 4; kk++) {
                const float xs = (kk == 0) ? x.x : (kk == 1) ? x.y : (kk == 2) ? x.z : x.w;
                const u64 a = pack2(xs, xs);
                const ulonglong2* w2 =
                    reinterpret_cast<const ulonglong2*>(cWe1p + (64 + u * 4 + kk) * 8);
#pragma unroll
                for (int q = 0; q < 4; q++) {
                    ulonglong2 w = w2[q];
                    h2[2 * q]     = ffma2(a, w.x, h2[2 * q]);
                    h2[2 * q + 1] = ffma2(a, w.y, h2[2 * q + 1]);
                }
            }
        }

        float h[16];
#pragma unroll
        for (int p = 0; p < 8; p++) {
            float lo, hi; unpack2(h2[p], lo, hi);
            h[2 * p]     = fmaxf(lo, 0.0f);
            h[2 * p + 1] = fmaxf(hi, 0.0f);
        }

        // layer 2
        u64 e2[8];
#pragma unroll
        for (int p = 0; p < 8; p++) e2[p] = be2p[p];
#pragma unroll
        for (int k = 0; k < 16; k++) {
            const u64 a = pack2(h[k], h[k]);
            const ulonglong2* w2 = reinterpret_cast<const ulonglong2*>(cWe2p + k * 8);
#pragma unroll
            for (int q = 0; q < 4; q++) {
                ulonglong2 w = w2[q];
                e2[2 * q]     = ffma2(a, w.x, e2[2 * q]);
                e2[2 * q + 1] = ffma2(a, w.y, e2[2 * q + 1]);
            }
        }

        float e[16];
#pragma unroll
        for (int p = 0; p < 8; p++) {
            float lo, hi; unpack2(e2[p], lo, hi);
            e[2 * p]     = fmaxf(lo, 0.0f);
            e[2 * p + 1] = fmaxf(hi, 0.0f);
        }

        float4* op = reinterpret_cast<float4*>(out_e + ((size_t)i * 1024 + j) * 16);
#pragma unroll
        for (int q = 0; q < 4; q++)
            op[q] = make_float4(e[4 * q], e[4 * q + 1], e[4 * q + 2], e[4 * q + 3]);

#pragma unroll
        for (int c = 0; c < 16; c++) msgb[c] += e[c];

        float total = warp_reduce16(e, lane);
        if (lane < 16) atomicAdd(&g_msga[i * 16 + chan16(lane)], total);
    }

#pragma unroll
    for (int c = 0; c < 16; c++) atomicAdd(&g_msgb[j * 16 + c], msgb[c]);
}

// ============ Kernel C: node MLP — warp per row, shfl-broadcast activations ============
__global__ __launch_bounds__(256) void node_kernel(const float* __restrict__ na,
                                                   const float* __restrict__ nb,
                                                   const float* __restrict__ Wn1,
                                                   const float* __restrict__ bn1,
                                                   const float* __restrict__ Wn2,
                                                   const float* __restrict__ bn2,
                                                   float* __restrict__ out_a,
                                                   float* __restrict__ out_b) {
    __shared__ __align__(16) float s1[48 * 32];
    __shared__ __align__(16) float s2[32 * 32];
    __shared__ __align__(16) float sb1[32];
    __shared__ __align__(16) float sb2[32];

    const int tid  = threadIdx.x;
    const int lane = tid & 31;
    const int wid  = tid >> 5;

#pragma unroll
    for (int q = 0; q < 3; q++)
        reinterpret_cast<float2*>(s1)[tid * 3 + q] =
            reinterpret_cast<const float2*>(Wn1)[tid * 3 + q];
    reinterpret_cast<float4*>(s2)[tid] = reinterpret_cast<const float4*>(Wn2)[tid];
    if (tid < 32) { sb1[tid] = bn1[tid]; sb2[tid] = bn2[tid]; }
    __syncthreads();

    const int row = blockIdx.x * 8 + wid;
    const float* node;
    const float* msg;
    float* out;
    if (row < N_NODES) {
        node = na + row * 32;  msg = g_msga + row * 16;  out = out_a + row * 32;
    } else {
        int rr = row - N_NODES;
        node = nb + rr * 32;   msg = g_msgb + rr * 16;   out = out_b + rr * 32;
    }

    const unsigned FULL = 0xffffffffu;
    float xa = node[lane];
    float xm = (lane < 16) ? msg[lane] : 0.0f;

    float h = sb1[lane];
#pragma unroll
    for (int k = 0; k < 32; k++) {
        float xs = __shfl_sync(FULL, xa, k);
        h = fmaf(xs, s1[k * 32 + lane], h);
    }
#pragma unroll
    for (int k = 0; k < 16; k++) {
        float xs = __shfl_sync(FULL, xm, k);
        h = fmaf(xs, s1[(32 + k) * 32 + lane], h);
    }
    h = fmaxf(h, 0.0f);

    float o = sb2[lane];
#pragma unroll
    for (int k = 0; k < 32; k++) {
        float hs = __shfl_sync(FULL, h, k);
        o = fmaf(hs, s2[k * 32 + lane], o);
    }
    out[lane] = fmaxf(o, 0.0f);
}

// ============ launch ============
extern "C" void kernel_launch(void* const* d_in, const int* in_sizes, int n_in,
                              void* d_out, int out_size) {
    const float* edges = (const float*)d_in[0];
    const float* na    = (const float*)d_in[1];
    const float* nb    = (const float*)d_in[2];
    const float* We1   = (const float*)d_in[3];
    const float* be1   = (const float*)d_in[4];
    const float* Wn1   = (const float*)d_in[7];
    const float* bn1   = (const float*)d_in[8];
    const float* Wn2   = (const float*)d_in[9];
    const float* bn2   = (const float*)d_in[10];

    cudaMemcpyToSymbolAsync(cWe1, d_in[3], 96 * 16 * sizeof(float), 0, cudaMemcpyDeviceToDevice);
    cudaMemcpyToSymbolAsync(cWe2, d_in[5], 16 * 16 * sizeof(float), 0, cudaMemcpyDeviceToDevice);
    cudaMemcpyToSymbolAsync(cbe2, d_in[6], 16 * sizeof(float),      0, cudaMemcpyDeviceToDevice);

    float* out_e = (float*)d_out;
    float* out_a = out_e + (size_t)1024 * 1024 * 16;
    float* out_b = out_a + 1024 * 32;

    static bool attr_set = false;
    if (!attr_set) {
        cudaFuncSetAttribute(edge_kernel, cudaFuncAttributeMaxDynamicSharedMemorySize,
                             EDGE_SMEM_BYTES);
        attr_set = true;
    }

    prep_kernel<<<32, 256>>>(na, nb, We1, be1);

    // 2 launches of 512 blocks: one wave each, and launch #6 across replays
    // (prep, eA, eB, node | prep, eA ...) is edge_kernel for the ncu slot.
    dim3 grid(8, 64);
    edge_kernel<<<grid, 128, EDGE_SMEM_BYTES>>>(edges, out_e, 0);
    edge_kernel<<<grid, 128, EDGE_SMEM_BYTES>>>(edges, out_e, 64);

    node_kernel<<<256, 256>>>(na, nb, Wn1, bn1, Wn2, bn2, out_a, out_b);
}

// round 13
// speedup vs baseline: 1.4503x; 1.4503x over previous
#include <cuda_runtime.h>
#include <cuda_bf16.h>

#define N_NODES 1024
#define ROWPAD 36                       // 32 data + 4 pad floats per staged row
#define WBUF_FLOATS (32 * ROWPAD)       // one warp buffer: 32 j-rows
#define NBUF 3
#define EDGE_SMEM_BYTES ((4 * NBUF * WBUF_FLOATS + 128) * 4)   // 55808 B

typedef unsigned long long u64;

// ---------------- packed f32x2 helpers (sm_103a) ----------------
__device__ __forceinline__ u64 pack2(float lo, float hi) {
    u64 r; asm("mov.b64 %0, {%1, %2};" : "=l"(r) : "f"(lo), "f"(hi)); return r;
}
__device__ __forceinline__ void unpack2(u64 v, float& lo, float& hi) {
    asm("mov.b64 {%0, %1}, %2;" : "=f"(lo), "=f"(hi) : "l"(v));
}
__device__ __forceinline__ u64 ffma2(u64 a, u64 b, u64 c) {
    u64 d; asm("fma.rn.f32x2 %0, %1, %2, %3;" : "=l"(d) : "l"(a), "l"(b), "l"(c)); return d;
}
__device__ __forceinline__ unsigned smem_u32(const void* p) {
    unsigned a;
    asm("{ .reg .u64 t; cvta.to.shared.u64 t, %1; cvt.u32.u64 %0, t; }" : "=r"(a) : "l"(p));
    return a;
}

// ---------------- constant weights for edge kernel ----------------
__constant__ float cWe1[96 * 16];
__constant__ float cbe2[16];
__constant__ float cWe2[16 * 16];

// ---------------- device scratch ----------------
__device__ __align__(16) float g_pa[N_NODES * 16];
__device__ __align__(16) float g_pb[N_NODES * 16];
__device__ __align__(16) float g_msga[N_NODES * 16];
__device__ __align__(16) float g_msgb[N_NODES * 16];

// ============ Kernel A: zero accumulators + per-node precompute ============
__global__ __launch_bounds__(256) void prep_kernel(const float* __restrict__ na,
                                                   const float* __restrict__ nb,
                                                   const float* __restrict__ We1,
                                                   const float* __restrict__ be1) {
    __shared__ __align__(16) float sw[32 * 16];
    __shared__ __align__(16) float sb[16];

    const int b    = blockIdx.x;
    const bool isA = (b < 16);
    const int bb   = isA ? b : b - 16;
    const int tid  = threadIdx.x;

    reinterpret_cast<float2*>(sw)[tid] =
        reinterpret_cast<const float2*>(We1 + (isA ? 0 : 512))[tid];
    if (tid < 16) sb[tid] = isA ? be1[tid] : 0.0f;

    reinterpret_cast<float4*>((isA ? g_msga : g_msgb) + bb * 1024)[tid] =
        make_float4(0.f, 0.f, 0.f, 0.f);
    __syncthreads();

    const int node = bb * 64 + (tid >> 2);
    const int cg   = (tid & 3) * 4;

    const float* row = (isA ? na : nb) + node * 32;
    float x[32];
#pragma unroll
    for (int u = 0; u < 8; u++) {
        float4 v = reinterpret_cast<const float4*>(row)[u];
        x[u * 4 + 0] = v.x; x[u * 4 + 1] = v.y; x[u * 4 + 2] = v.z; x[u * 4 + 3] = v.w;
    }

    float4 acc = *reinterpret_cast<const float4*>(&sb[cg]);
#pragma unroll
    for (int k = 0; k < 32; k++) {
        const float xs = x[k];
        float4 w = *reinterpret_cast<const float4*>(&sw[k * 16 + cg]);
        acc.x = fmaf(xs, w.x, acc.x);
        acc.y = fmaf(xs, w.y, acc.y);
        acc.z = fmaf(xs, w.z, acc.z);
        acc.w = fmaf(xs, w.w, acc.w);
    }

    float* dst = (isA ? g_pa : g_pb) + node * 16 + cg;
    *reinterpret_cast<float4*>(dst) = acc;
}

// Butterfly channel-merging reduction.
__device__ __forceinline__ int chan16(int lane) {
    return ((lane & 1) ? 8 : 0) | ((lane & 2) ? 4 : 0) |
           ((lane & 4) ? 2 : 0) | ((lane & 8) ? 1 : 0);
}

__device__ __forceinline__ float warp_reduce16(float* v, int lane) {
    const unsigned FULL = 0xffffffffu;
    {
        bool hi = (lane & 1);
#pragma unroll
        for (int k = 0; k < 8; k++) {
            float send  = hi ? v[k] : v[k + 8];
            float other = __shfl_xor_sync(FULL, send, 1);
            v[k] = (hi ? v[k + 8] : v[k]) + other;
        }
    }
    {
        bool hi = (lane & 2);
#pragma unroll
        for (int k = 0; k < 4; k++) {
            float send  = hi ? v[k] : v[k + 4];
            float other = __shfl_xor_sync(FULL, send, 2);
            v[k] = (hi ? v[k + 4] : v[k]) + other;
        }
    }
    {
        bool hi = (lane & 4);
#pragma unroll
        for (int k = 0; k < 2; k++) {
            float send  = hi ? v[k] : v[k + 2];
            float other = __shfl_xor_sync(FULL, send, 4);
            v[k] = (hi ? v[k + 2] : v[k]) + other;
        }
    }
    {
        bool hi = (lane & 8);
        float send  = hi ? v[0] : v[1];
        float other = __shfl_xor_sync(FULL, send, 8);
        v[0] = (hi ? v[1] : v[0]) + other;
    }
    v[0] += __shfl_xor_sync(FULL, v[0], 16);
    return v[0];
}

// ============ Kernel B: edge MLP — per-WARP private triple-buffer pipeline ============
// Each warp stages ONLY its own 32-j slice; cp.async.wait_group + __syncwarp
// replaces all block-wide barriers. Warps are fully decoupled.
__global__ __launch_bounds__(128) void edge_kernel(const float* __restrict__ edges,
                                                   float* __restrict__ out_e) {
    extern __shared__ __align__(16) float smem[];
    float* s_pa = smem + 4 * NBUF * WBUF_FLOATS;

    const int tid  = threadIdx.x;
    const int lane = tid & 31;
    const int w    = tid >> 5;
    const int j0   = blockIdx.x * 128;
    const int j    = j0 + tid;
    const int i0   = blockIdx.y * 8;

    float* wbase = smem + w * NBUF * WBUF_FLOATS;   // this warp's buffers

    s_pa[tid] = g_pa[i0 * 16 + tid];

    const u64* cWe1p = reinterpret_cast<const u64*>(cWe1);
    const u64* cWe2p = reinterpret_cast<const u64*>(cWe2);

    u64 pb2[8];
    {
        const float4* p4 = reinterpret_cast<const float4*>(g_pb + j * 16);
#pragma unroll
        for (int u = 0; u < 4; u++) {
            float4 v = p4[u];
            pb2[2 * u]     = pack2(v.x, v.y);
            pb2[2 * u + 1] = pack2(v.z, v.w);
        }
    }
    u64 be2p[8];
#pragma unroll
    for (int p = 0; p < 8; p++) be2p[p] = pack2(cbe2[2 * p], cbe2[2 * p + 1]);

    float msgb[16];
#pragma unroll
    for (int c = 0; c < 16; c++) msgb[c] = 0.0f;

    // stage this warp's 32-j slice of i-row into warp-private slot
    auto stage = [&](int i_row, int slot) {
        const float* srcbase = edges + ((size_t)i_row * 1024 + j0 + w * 32) * 32;
        unsigned dstbase = smem_u32(wbase + slot * WBUF_FLOATS);
#pragma unroll
        for (int q = 0; q < 8; q++) {
            int g   = q * 32 + lane;     // 16B chunks, coalesced within warp
            int row = g >> 3;
            int kk  = g & 7;
            unsigned d = dstbase + (unsigned)(row * ROWPAD + kk * 4) * 4u;
            const float* s = srcbase + g * 4;
            asm volatile("cp.async.cg.shared.global [%0], [%1], 16;" :: "r"(d), "l"(s));
        }
        asm volatile("cp.async.commit_group;");
    };

    // one block-wide barrier total: s_pa visibility
    stage(i0 + 0, 0);
    stage(i0 + 1, 1);
    stage(i0 + 2, 2);
    __syncthreads();

#pragma unroll 1
    for (int it = 0; it < 8; it++) {
        const int i = i0 + it;
        const int slot = it % 3;

        if (it <= 5)      asm volatile("cp.async.wait_group 2;");
        else if (it == 6) asm volatile("cp.async.wait_group 1;");
        else              asm volatile("cp.async.wait_group 0;");
        __syncwarp();

        const float* myrow = wbase + slot * WBUF_FLOATS + lane * ROWPAD;

        // layer 1: h = pa[i] + pb[j] + edge @ We1[64:96]
        u64 h2[8];
#pragma unroll
        for (int p = 0; p < 8; p++) {
            float alo = s_pa[it * 16 + 2 * p];
            float ahi = s_pa[it * 16 + 2 * p + 1];
            float blo, bhi; unpack2(pb2[p], blo, bhi);
            h2[p] = pack2(alo + blo, ahi + bhi);
        }

#pragma unroll
        for (int u = 0; u < 8; u++) {
            float4 x = *reinterpret_cast<const float4*>(myrow + u * 4);
#pragma unroll
            for (int kk = 0; kk < 4; kk++) {
                const float xs = (kk == 0) ? x.x : (kk == 1) ? x.y : (kk == 2) ? x.z : x.w;
                const u64 a = pack2(xs, xs);
                const ulonglong2* w2 =
                    reinterpret_cast<const ulonglong2*>(cWe1p + (64 + u * 4 + kk) * 8);
#pragma unroll
                for (int q = 0; q < 4; q++) {
                    ulonglong2 wq = w2[q];
                    h2[2 * q]     = ffma2(a, wq.x, h2[2 * q]);
                    h2[2 * q + 1] = ffma2(a, wq.y, h2[2 * q + 1]);
                }
            }
        }

        float h[16];
#pragma unroll
        for (int p = 0; p < 8; p++) {
            float lo, hi; unpack2(h2[p], lo, hi);
            h[2 * p]     = fmaxf(lo, 0.0f);
            h[2 * p + 1] = fmaxf(hi, 0.0f);
        }

        // layer 2
        u64 e2[8];
#pragma unroll
        for (int p = 0; p < 8; p++) e2[p] = be2p[p];
#pragma unroll
        for (int k = 0; k < 16; k++) {
            const u64 a = pack2(h[k], h[k]);
            const ulonglong2* w2 = reinterpret_cast<const ulonglong2*>(cWe2p + k * 8);
#pragma unroll
            for (int q = 0; q < 4; q++) {
                ulonglong2 wq = w2[q];
                e2[2 * q]     = ffma2(a, wq.x, e2[2 * q]);
                e2[2 * q + 1] = ffma2(a, wq.y, e2[2 * q + 1]);
            }
        }

        float e[16];
#pragma unroll
        for (int p = 0; p < 8; p++) {
            float lo, hi; unpack2(e2[p], lo, hi);
            e[2 * p]     = fmaxf(lo, 0.0f);
            e[2 * p + 1] = fmaxf(hi, 0.0f);
        }

        float4* op = reinterpret_cast<float4*>(out_e + ((size_t)i * 1024 + j) * 16);
#pragma unroll
        for (int q = 0; q < 4; q++)
            op[q] = make_float4(e[4 * q], e[4 * q + 1], e[4 * q + 2], e[4 * q + 3]);

#pragma unroll
        for (int c = 0; c < 16; c++) msgb[c] += e[c];

        float total = warp_reduce16(e, lane);
        if (lane < 16) atomicAdd(&g_msga[i * 16 + chan16(lane)], total);

        __syncwarp();                    // warp's reads of this slot done
        if (it + 3 < 8) stage(i0 + it + 3, slot);
    }

#pragma unroll
    for (int c = 0; c < 16; c++) atomicAdd(&g_msgb[j * 16 + c], msgb[c]);
}

// ============ Kernel C: node MLP — warp per row, shfl-broadcast activations ============
__global__ __launch_bounds__(256) void node_kernel(const float* __restrict__ na,
                                                   const float* __restrict__ nb,
                                                   const float* __restrict__ Wn1,
                                                   const float* __restrict__ bn1,
                                                   const float* __restrict__ Wn2,
                                                   const float* __restrict__ bn2,
                                                   float* __restrict__ out_a,
                                                   float* __restrict__ out_b) {
    __shared__ __align__(16) float s1[48 * 32];
    __shared__ __align__(16) float s2[32 * 32];
    __shared__ __align__(16) float sb1[32];
    __shared__ __align__(16) float sb2[32];

    const int tid  = threadIdx.x;
    const int lane = tid & 31;
    const int wid  = tid >> 5;

#pragma unroll
    for (int q = 0; q < 3; q++)
        reinterpret_cast<float2*>(s1)[tid * 3 + q] =
            reinterpret_cast<const float2*>(Wn1)[tid * 3 + q];
    reinterpret_cast<float4*>(s2)[tid] = reinterpret_cast<const float4*>(Wn2)[tid];
    if (tid < 32) { sb1[tid] = bn1[tid]; sb2[tid] = bn2[tid]; }
    __syncthreads();

    const int row = blockIdx.x * 8 + wid;
    const float* node;
    const float* msg;
    float* out;
    if (row < N_NODES) {
        node = na + row * 32;  msg = g_msga + row * 16;  out = out_a + row * 32;
    } else {
        int rr = row - N_NODES;
        node = nb + rr * 32;   msg = g_msgb + rr * 16;   out = out_b + rr * 32;
    }

    const unsigned FULL = 0xffffffffu;
    float xa = node[lane];
    float xm = (lane < 16) ? msg[lane] : 0.0f;

    float h = sb1[lane];
#pragma unroll
    for (int k = 0; k < 32; k++) {
        float xs = __shfl_sync(FULL, xa, k);
        h = fmaf(xs, s1[k * 32 + lane], h);
    }
#pragma unroll
    for (int k = 0; k < 16; k++) {
        float xs = __shfl_sync(FULL, xm, k);
        h = fmaf(xs, s1[(32 + k) * 32 + lane], h);
    }
    h = fmaxf(h, 0.0f);

    float o = sb2[lane];
#pragma unroll
    for (int k = 0; k < 32; k++) {
        float hs = __shfl_sync(FULL, h, k);
        o = fmaf(hs, s2[k * 32 + lane], o);
    }
    out[lane] = fmaxf(o, 0.0f);
}

// ============ launch ============
extern "C" void kernel_launch(void* const* d_in, const int* in_sizes, int n_in,
                              void* d_out, int out_size) {
    const float* edges = (const float*)d_in[0];
    const float* na    = (const float*)d_in[1];
    const float* nb    = (const float*)d_in[2];
    const float* We1   = (const float*)d_in[3];
    const float* be1   = (const float*)d_in[4];
    const float* Wn1   = (const float*)d_in[7];
    const float* bn1   = (const float*)d_in[8];
    const float* Wn2   = (const float*)d_in[9];
    const float* bn2   = (const float*)d_in[10];

    cudaMemcpyToSymbolAsync(cWe1, d_in[3], 96 * 16 * sizeof(float), 0, cudaMemcpyDeviceToDevice);
    cudaMemcpyToSymbolAsync(cWe2, d_in[5], 16 * 16 * sizeof(float), 0, cudaMemcpyDeviceToDevice);
    cudaMemcpyToSymbolAsync(cbe2, d_in[6], 16 * sizeof(float),      0, cudaMemcpyDeviceToDevice);

    float* out_e = (float*)d_out;
    float* out_a = out_e + (size_t)1024 * 1024 * 16;
    float* out_b = out_a + 1024 * 32;

    static bool attr_set = false;
    if (!attr_set) {
        cudaFuncSetAttribute(edge_kernel, cudaFuncAttributeMaxDynamicSharedMemorySize,
                             EDGE_SMEM_BYTES);
        attr_set = true;
    }

    prep_kernel<<<32, 256>>>(na, nb, We1, be1);

    dim3 grid(8, 128);   // single launch, 1024 blocks
    edge_kernel<<<grid, 128, EDGE_SMEM_BYTES>>>(edges, out_e);

    node_kernel<<<256, 256>>>(na, nb, Wn1, bn1, Wn2, bn2, out_a, out_b);
}